// round 1
// baseline (speedup 1.0000x reference)
#include <cuda_runtime.h>

#define LLEN 1024
#define NB   64
#define TILE 128

// ---- device scratch (no allocations allowed) ----
__device__ float g_cat [NB * 192 * LLEN];   // encoder concat features (6 x 32 ch)
__device__ float g_dec [NB * 192 * LLEN];   // decoder concat features (6 x 32 ch)
__device__ float g_encU[NB * 64  * LLEN];   // compressed+pooled+upsampled encoding
__device__ int   g_ids [NB];

// ------------------------------------------------------------------
// ids: last column of x, float -> int
// ------------------------------------------------------------------
__global__ void ids_kernel(const float* __restrict__ x) {
    int b = threadIdx.x;
    if (b < NB) g_ids[b] = (int)x[(long)b * (LLEN + 1) + LLEN];
}

// ------------------------------------------------------------------
// Fused block: y = relu(W2 @ relu(dilated_conv5(x, W1) + b1) + b2)
//   conv1: Cin -> 128, k=5, dilation d, SAME padding (pad 2d each side)
//   conv2: 128 -> 32, 1x1
// Grid: (L/TILE, B), 512 threads.
// smem: xs[CIN][256] | ws1[CCH][128][5] | hs[128][TILE] | ws2[32][128] | b1s | b2s
// ------------------------------------------------------------------
template<int CIN>
__global__ void __launch_bounds__(512, 1)
block_kernel(const float* __restrict__ xin, long in_samp_stride, int in_ch_stride,
             const float* __restrict__ w1, const float* __restrict__ b1,
             const float* __restrict__ w2, const float* __restrict__ b2,
             float* __restrict__ yout, long out_samp_stride,
             int dil,
             const int* __restrict__ ids,
             long w1_cs, long b1_cs, long w2_cs, long b2_cs)
{
    constexpr int CCH = (CIN < 16) ? CIN : 16;
    extern __shared__ float sm[];
    float* xs  = sm;                       // CIN * 256
    float* ws1 = xs  + CIN * 256;          // CCH * 128 * 5
    float* hs  = ws1 + CCH * 128 * 5;      // 128 * TILE
    float* ws2 = hs  + 128 * TILE;         // 32 * 128
    float* b1s = ws2 + 32 * 128;           // 128
    float* b2s = b1s + 128;                // 32

    const int b    = blockIdx.y;
    const int l0   = blockIdx.x * TILE;
    const int tid  = threadIdx.x;
    const int warp = tid >> 5;
    const int ln   = tid & 31;

    const float* w1p = w1;
    const float* b1p = b1;
    const float* w2p = w2;
    const float* b2p = b2;
    if (ids) {
        int c = ids[b];
        w1p += (long)c * w1_cs;  b1p += (long)c * b1_cs;
        w2p += (long)c * w2_cs;  b2p += (long)c * b2_cs;
    }

    // ---- stage input tile (with halo, zero-padded) ----
    const float* xb = xin + (long)b * in_samp_stride;
    for (int i = tid; i < CIN * 256; i += 512) {
        int ci = i >> 8, j = i & 255;
        int pos = l0 - 2 * dil + j;
        xs[i] = (pos >= 0 && pos < LLEN) ? xb[(long)ci * in_ch_stride + pos] : 0.f;
    }
    if (tid < 128) b1s[tid] = b1p[tid];
    if (tid < 32)  b2s[tid] = b2p[tid];
    for (int i = tid; i < 32 * 128; i += 512) ws2[i] = w2p[i];

    // ---- conv1: warp owns co = warp*8 .. +8, lane owns l = ln + 32*i ----
    float acc[8][4];
    #pragma unroll
    for (int c = 0; c < 8; c++)
        #pragma unroll
        for (int i = 0; i < 4; i++) acc[c][i] = 0.f;

    for (int ci0 = 0; ci0 < CIN; ci0 += CCH) {
        __syncthreads();   // protects ws1 reuse (and initial staging on iter 0)
        const int cnt = CCH * 128 * 5;
        for (int i = tid; i < cnt; i += 512) {
            int co  = i / (CCH * 5);
            int r   = i - co * (CCH * 5);
            int cil = r / 5;
            int t   = r - cil * 5;
            ws1[cil * 640 + co * 5 + t] =
                w1p[(long)co * (CIN * 5) + (ci0 + cil) * 5 + t];
        }
        __syncthreads();
        #pragma unroll
        for (int cil = 0; cil < CCH; cil++) {
            const float* xrow = xs + (ci0 + cil) * 256;
            const float* wrow = ws1 + cil * 640 + (warp * 8) * 5;
            #pragma unroll
            for (int t = 0; t < 5; t++) {
                float xv[4];
                #pragma unroll
                for (int i = 0; i < 4; i++) xv[i] = xrow[ln + 32 * i + t * dil];
                #pragma unroll
                for (int c = 0; c < 8; c++) {
                    float wv = wrow[c * 5 + t];
                    #pragma unroll
                    for (int i = 0; i < 4; i++) acc[c][i] = fmaf(wv, xv[i], acc[c][i]);
                }
            }
        }
    }
    __syncthreads();
    // ---- bias + relu -> hs ----
    #pragma unroll
    for (int c = 0; c < 8; c++) {
        int co = warp * 8 + c;
        float bb = b1s[co];
        #pragma unroll
        for (int i = 0; i < 4; i++) {
            float v = acc[c][i] + bb;
            hs[co * TILE + ln + 32 * i] = v > 0.f ? v : 0.f;
        }
    }
    __syncthreads();

    // ---- conv2 (1x1, 128 -> 32): warp owns co2 = warp*2 + {0,1} ----
    float a2[2][4];
    #pragma unroll
    for (int c = 0; c < 2; c++)
        #pragma unroll
        for (int i = 0; i < 4; i++) a2[c][i] = 0.f;

    const float* w2r0 = ws2 + (warp * 2 + 0) * 128;
    const float* w2r1 = ws2 + (warp * 2 + 1) * 128;
    #pragma unroll 4
    for (int k = 0; k < 128; k++) {
        float xv[4];
        #pragma unroll
        for (int i = 0; i < 4; i++) xv[i] = hs[k * TILE + ln + 32 * i];
        float wv0 = w2r0[k], wv1 = w2r1[k];
        #pragma unroll
        for (int i = 0; i < 4; i++) {
            a2[0][i] = fmaf(wv0, xv[i], a2[0][i]);
            a2[1][i] = fmaf(wv1, xv[i], a2[1][i]);
        }
    }

    float* yb = yout + (long)b * out_samp_stride;
    #pragma unroll
    for (int c = 0; c < 2; c++) {
        int co2 = warp * 2 + c;
        float bb = b2s[co2];
        #pragma unroll
        for (int i = 0; i < 4; i++) {
            float v = a2[c][i] + bb;
            yb[(long)co2 * LLEN + l0 + ln + 32 * i] = v > 0.f ? v : 0.f;
        }
    }
}

// ------------------------------------------------------------------
// compress conv (192 -> 64, 1x1, no relu) fused with avgpool(2)+repeat(2)
// Grid: (L/TILE, B), 512 threads.
// ------------------------------------------------------------------
__global__ void __launch_bounds__(512, 1)
comp_kernel(const float* __restrict__ cat, const float* __restrict__ cw,
            const float* __restrict__ cb, float* __restrict__ out)
{
    extern __shared__ float sm[];
    float* xs  = sm;                  // 192 * 128
    float* ws  = xs + 192 * 128;      // 64 * 192
    float* cbs = ws + 64 * 192;       // 64

    const int b    = blockIdx.y;
    const int l0   = blockIdx.x * TILE;
    const int tid  = threadIdx.x;
    const int warp = tid >> 5;
    const int ln   = tid & 31;

    const float* catb = cat + (long)b * 192 * LLEN;
    for (int i = tid; i < 192 * 128; i += 512) {
        int ch = i >> 7, j = i & 127;
        xs[i] = catb[(long)ch * LLEN + l0 + j];
    }
    for (int i = tid; i < 64 * 192; i += 512) ws[i] = cw[i];
    if (tid < 64) cbs[tid] = cb[tid];
    __syncthreads();

    float acc[4][4];
    #pragma unroll
    for (int c = 0; c < 4; c++)
        #pragma unroll
        for (int i = 0; i < 4; i++) acc[c][i] = 0.f;

    const float* wrow = ws + (warp * 4) * 192;
    #pragma unroll 4
    for (int k = 0; k < 192; k++) {
        float xv[4];
        #pragma unroll
        for (int i = 0; i < 4; i++) xv[i] = xs[k * 128 + ln + 32 * i];
        #pragma unroll
        for (int c = 0; c < 4; c++) {
            float wv = wrow[c * 192 + k];
            #pragma unroll
            for (int i = 0; i < 4; i++) acc[c][i] = fmaf(wv, xv[i], acc[c][i]);
        }
    }

    float* ob = out + (long)b * 64 * LLEN;
    #pragma unroll
    for (int c = 0; c < 4; c++) {
        int co = warp * 4 + c;
        float bb = cbs[co];
        #pragma unroll
        for (int i = 0; i < 4; i++) {
            float v = acc[c][i] + bb;
            // avgpool(2) + nearest upsample(2): lanes (2m,2m+1) hold l pair
            float v2 = __shfl_xor_sync(0xffffffffu, v, 1);
            ob[(long)co * LLEN + l0 + ln + 32 * i] = 0.5f * (v + v2);
        }
    }
}

// ------------------------------------------------------------------
// final per-sample 1x1 conv: 192 -> 1, weights selected by combination id
// ------------------------------------------------------------------
__global__ void __launch_bounds__(256, 1)
final_kernel(const float* __restrict__ dec, const float* __restrict__ cw,
             const float* __restrict__ cbv, float* __restrict__ out)
{
    __shared__ float ws[192];
    const int b   = blockIdx.x;
    const int tid = threadIdx.x;
    const int c   = g_ids[b];
    if (tid < 192) ws[tid] = cw[(long)c * 192 + tid];
    __syncthreads();
    const float bb = cbv[c];
    const float* db = dec + (long)b * 192 * LLEN;
    for (int l = tid; l < LLEN; l += 256) {
        float s = bb;
        #pragma unroll 8
        for (int ch = 0; ch < 192; ch++) s = fmaf(ws[ch], db[(long)ch * LLEN + l], s);
        out[(long)b * LLEN + l] = s;
    }
}

// ------------------------------------------------------------------
static constexpr int smem_block(int cin) {
    int cch = cin < 16 ? cin : 16;
    return (cin * 256 + cch * 640 + 128 * TILE + 32 * 128 + 160) * 4;
}
static constexpr int SMEM_C = (192 * 128 + 64 * 192 + 64) * 4;

extern "C" void kernel_launch(void* const* d_in, const int* in_sizes, int n_in,
                              void* d_out, int out_size)
{
    const float* x        = (const float*)d_in[0];
    const float* enc0_w1  = (const float*)d_in[1];
    const float* enc0_b1  = (const float*)d_in[2];
    const float* enc0_w2  = (const float*)d_in[3];
    const float* enc0_b2  = (const float*)d_in[4];
    const float* enc_w1   = (const float*)d_in[5];
    const float* enc_b1   = (const float*)d_in[6];
    const float* enc_w2   = (const float*)d_in[7];
    const float* enc_b2   = (const float*)d_in[8];
    const float* comp_w   = (const float*)d_in[9];
    const float* comp_b   = (const float*)d_in[10];
    const float* decf0_w1 = (const float*)d_in[11];
    const float* decf0_b1 = (const float*)d_in[12];
    const float* decf0_w2 = (const float*)d_in[13];
    const float* decf0_b2 = (const float*)d_in[14];
    const float* decf_w1  = (const float*)d_in[15];
    const float* decf_b1  = (const float*)d_in[16];
    const float* decf_w2  = (const float*)d_in[17];
    const float* decf_b2  = (const float*)d_in[18];
    const float* decv_w1  = (const float*)d_in[19];
    const float* decv_b1  = (const float*)d_in[20];
    const float* decv_w2  = (const float*)d_in[21];
    const float* decv_b2  = (const float*)d_in[22];
    const float* decv_cw  = (const float*)d_in[23];
    const float* decv_cb  = (const float*)d_in[24];
    float* out = (float*)d_out;

    float *cat, *dec, *encU;
    int* idsp;
    cudaGetSymbolAddress((void**)&cat,  g_cat);
    cudaGetSymbolAddress((void**)&dec,  g_dec);
    cudaGetSymbolAddress((void**)&encU, g_encU);
    cudaGetSymbolAddress((void**)&idsp, g_ids);
    (void)idsp;

    cudaFuncSetAttribute(block_kernel<1>,  cudaFuncAttributeMaxDynamicSharedMemorySize, smem_block(1));
    cudaFuncSetAttribute(block_kernel<32>, cudaFuncAttributeMaxDynamicSharedMemorySize, smem_block(32));
    cudaFuncSetAttribute(block_kernel<64>, cudaFuncAttributeMaxDynamicSharedMemorySize, smem_block(64));
    cudaFuncSetAttribute(comp_kernel,      cudaFuncAttributeMaxDynamicSharedMemorySize, SMEM_C);

    const dim3 grid(LLEN / TILE, NB);
    const long SS = (long)192 * LLEN;  // sample stride of concat buffers

    ids_kernel<<<1, 64>>>(x);

    // ---- encoder ----
    block_kernel<1><<<grid, 512, smem_block(1)>>>(
        x, (long)(LLEN + 1), 0,
        enc0_w1, enc0_b1, enc0_w2, enc0_b2,
        cat, SS, 1, nullptr, 0, 0, 0, 0);
    for (int j = 1; j < 6; j++) {
        block_kernel<32><<<grid, 512, smem_block(32)>>>(
            cat + (long)(j - 1) * 32 * LLEN, SS, LLEN,
            enc_w1 + (long)(j - 1) * 20480, enc_b1 + (j - 1) * 128,
            enc_w2 + (long)(j - 1) * 4096,  enc_b2 + (j - 1) * 32,
            cat + (long)j * 32 * LLEN, SS, 1 << j, nullptr, 0, 0, 0, 0);
    }

    // ---- compress + pool + upsample ----
    comp_kernel<<<grid, 512, SMEM_C>>>(cat, comp_w, comp_b, encU);

    // ---- fixed decoder ----
    block_kernel<64><<<grid, 512, smem_block(64)>>>(
        encU, (long)64 * LLEN, LLEN,
        decf0_w1, decf0_b1, decf0_w2, decf0_b2,
        dec, SS, 32, nullptr, 0, 0, 0, 0);
    for (int j = 1; j < 4; j++) {
        block_kernel<32><<<grid, 512, smem_block(32)>>>(
            dec + (long)(j - 1) * 32 * LLEN, SS, LLEN,
            decf_w1 + (long)(j - 1) * 20480, decf_b1 + (j - 1) * 128,
            decf_w2 + (long)(j - 1) * 4096,  decf_b2 + (j - 1) * 32,
            dec + (long)j * 32 * LLEN, SS, 1 << (5 - j), nullptr, 0, 0, 0, 0);
    }

    // ---- variable decoder: only the per-sample selected combination ----
    for (int j = 0; j < 2; j++) {
        block_kernel<32><<<grid, 512, smem_block(32)>>>(
            dec + (long)(3 + j) * 32 * LLEN, SS, LLEN,
            decv_w1 + (long)j * 20480, decv_b1 + j * 128,
            decv_w2 + (long)j * 4096,  decv_b2 + j * 32,
            dec + (long)(4 + j) * 32 * LLEN, SS, 1 << (1 - j),
            idsp, 40960, 256, 8192, 64);
    }

    // ---- final 1x1 conv (per-sample weights) ----
    final_kernel<<<NB, 256>>>(dec, decv_cw, decv_cb, out);
}